// round 16
// baseline (speedup 1.0000x reference)
#include <cuda_runtime.h>
#include <cuda_fp16.h>
#include <cstdint>

#define DIMC  1024
#define NH    16
#define HD    64
#define BATCH 4
#define SEQ   2048
#define MTOT  (BATCH*SEQ)   // 8192

// ---------------- scratch (device globals; no allocation allowed) ----------
__device__ __half g_xh[(size_t)MTOT*DIMC];        // x in fp16
__device__ __half g_wh[(size_t)4*DIMC*DIMC];      // wq,wk,wv,wo in fp16
__device__ __half g_q[(size_t)MTOT*DIMC];         // [b*NH+h][t][d], pre-scaled by log2e/8
__device__ __half g_k[(size_t)MTOT*DIMC];
__device__ __half g_v[(size_t)MTOT*DIMC];
__device__ __half g_attn[(size_t)MTOT*DIMC];      // [b*T+t][h*64+d]

// ---------------- helpers ---------------------------------------------------
__device__ __forceinline__ uint32_t smem_u32(const void* p){
    uint32_t a;
    asm("{ .reg .u64 t; cvta.to.shared.u64 t, %1; cvt.u32.u64 %0, t; }" : "=r"(a) : "l"(p));
    return a;
}
// pack two f32 -> f16x2 (lo, hi). PTX cvt f16x2: first source -> HIGH half.
__device__ __forceinline__ uint32_t packh2(float lo, float hi){
    uint32_t d;
    asm("cvt.rn.f16x2.f32 %0, %1, %2;" : "=r"(d) : "f"(hi), "f"(lo));
    return d;
}
__device__ __forceinline__ float ex2(float x){
    float r; asm("ex2.approx.f32 %0, %1;" : "=f"(r) : "f"(x)); return r;
}
__device__ __forceinline__ void cp16(uint32_t dst, const void* src){
    asm volatile("cp.async.cg.shared.global [%0], [%1], 16;" :: "r"(dst), "l"(src));
}
#define CP_COMMIT() asm volatile("cp.async.commit_group;" ::: "memory")
#define CP_WAIT(n)  asm volatile("cp.async.wait_group %0;" :: "n"(n) : "memory")

__device__ __forceinline__ void ldsm_x4(uint32_t& r0, uint32_t& r1, uint32_t& r2, uint32_t& r3,
                                        uint32_t addr){
    asm volatile("ldmatrix.sync.aligned.m8n8.x4.shared.b16 {%0,%1,%2,%3}, [%4];"
                 : "=r"(r0), "=r"(r1), "=r"(r2), "=r"(r3) : "r"(addr));
}
__device__ __forceinline__ void ldsm_x4t(uint32_t& r0, uint32_t& r1, uint32_t& r2, uint32_t& r3,
                                         uint32_t addr){
    asm volatile("ldmatrix.sync.aligned.m8n8.x4.trans.shared.b16 {%0,%1,%2,%3}, [%4];"
                 : "=r"(r0), "=r"(r1), "=r"(r2), "=r"(r3) : "r"(addr));
}
__device__ __forceinline__ void mma_f16(float c[4], const uint32_t a[4], const uint32_t b[2]){
    asm volatile(
        "mma.sync.aligned.m16n8k16.row.col.f32.f16.f16.f32 "
        "{%0,%1,%2,%3}, {%4,%5,%6,%7}, {%8,%9}, {%0,%1,%2,%3};"
        : "+f"(c[0]), "+f"(c[1]), "+f"(c[2]), "+f"(c[3])
        : "r"(a[0]), "r"(a[1]), "r"(a[2]), "r"(a[3]), "r"(b[0]), "r"(b[1]));
}

// ---------------- fp32 -> fp16 converts --------------------------------------
__global__ void cvt_x_f16(const float* __restrict__ src, int n8){
    int i = blockIdx.x*blockDim.x + threadIdx.x;
    if (i >= n8) return;
    float4 a = ((const float4*)src)[2*i];
    float4 b = ((const float4*)src)[2*i + 1];
    uint4 o;
    o.x = packh2(a.x, a.y); o.y = packh2(a.z, a.w);
    o.z = packh2(b.x, b.y); o.w = packh2(b.z, b.w);
    ((uint4*)g_xh)[i] = o;
}
__global__ void cvt_w_f16(const float* __restrict__ w0, const float* __restrict__ w1,
                          const float* __restrict__ w2, const float* __restrict__ w3,
                          int n8){
    int i = blockIdx.x*blockDim.x + threadIdx.x;
    if (i >= n8) return;
    int z = blockIdx.y;
    const float* src = (z == 0) ? w0 : (z == 1) ? w1 : (z == 2) ? w2 : w3;
    __half* dst = g_wh + (size_t)z*DIMC*DIMC;
    float4 a = ((const float4*)src)[2*i];
    float4 b = ((const float4*)src)[2*i + 1];
    uint4 o;
    o.x = packh2(a.x, a.y); o.y = packh2(a.z, a.w);
    o.z = packh2(b.x, b.y); o.w = packh2(b.z, b.w);
    ((uint4*)dst)[i] = o;
}

// ============================================================================
// fp16 GEMM:  C[M,N] = A[M,K] @ W[N,K]^T   (both K-major fp16, K=1024)
// 128x128 tile, 8 warps (2x4), warp tile 64x32, BK=64 (16 k-iterations),
// 3-stage cp.async pipeline (2 tile-fills in flight -> L2 latency covered),
// rows 144 B (attn-proven conflict-free ldmatrix layout). 2 CTAs/SM.
// ============================================================================
#define BM 128
#define BN 128
#define GK 64
#define GNT2 (DIMC/GK)        // 16
#define GRB 144               // bytes per smem row (64 halves + 8 pad)
#define ATB (BM*GRB)          // bytes per operand tile: 18432
#define STAGE_B (2*ATB)       // 36864 B per stage
#define NSTG 3
#define GSMEM_BYTES (NSTG*STAGE_B)   // 110592

__device__ __forceinline__ void g_fill(uint32_t sbase, int st,
                                       const __half* __restrict__ A,
                                       const __half* __restrict__ W,
                                       int bm0, int bn0, int kt, int tid){
    uint32_t sd = sbase + (uint32_t)(st*STAGE_B);
    #pragma unroll
    for (int p = 0; p < 8; p++){
        int n = tid + p*256;            // 0..2047
        int op = n >> 10, m = n & 1023; // op 0=A, 1=B
        int r = m >> 3, ch = m & 7;     // row 0..127, 16B chunk 0..7
        const __half* src = op ? (W + (size_t)(bn0 + r)*DIMC + kt*GK + ch*8)
                               : (A + (size_t)(bm0 + r)*DIMC + kt*GK + ch*8);
        cp16(sd + (uint32_t)(op*ATB + r*GRB + ch*16), src);
    }
}

__global__ void __launch_bounds__(256, 2)
gemm_f16(float* __restrict__ Cout, int qkv)
{
    extern __shared__ __align__(16) __half sm[];
    uint32_t sbase = smem_u32(sm);
    int tid = threadIdx.x, lane = tid & 31, warp = tid >> 5;
    int bm0 = blockIdx.y*BM, bn0 = blockIdx.x*BN;
    int z = qkv ? (int)blockIdx.z : 3;
    const __half* A = qkv ? g_xh : g_attn;
    const __half* W = g_wh + (size_t)z*DIMC*DIMC;
    int wm = (warp >> 2)*64, wn = (warp & 3)*32;   // 2x4 warp grid, tile 64x32

    // per-lane ldmatrix byte offsets (attn-proven patterns, loop-invariant)
    uint32_t aOff = (uint32_t)((wm + (lane & 15))*GRB + ((lane & 16) ? 16 : 0));
    uint32_t bOff = (uint32_t)(ATB + (wn + (lane & 7) + ((lane & 16) ? 8 : 0))*GRB
                               + ((lane & 8) << 1));

    float c[4][4][4];
    #pragma unroll
    for (int i = 0; i < 4; i++)
        #pragma unroll
        for (int j = 0; j < 4; j++)
            #pragma unroll
            for (int k = 0; k < 4; k++) c[i][j][k] = 0.f;

    g_fill(sbase, 0, A, W, bm0, bn0, 0, tid); CP_COMMIT();
    g_fill(sbase, 1, A, W, bm0, bn0, 1, tid); CP_COMMIT();

    for (int kt = 0; kt < GNT2; kt++){
        int s = kt % 3;
        if (kt < GNT2-1) { CP_WAIT(1); } else { CP_WAIT(0); }
        __syncthreads();
        if (kt + 2 < GNT2){
            g_fill(sbase, (kt+2) % 3, A, W, bm0, bn0, kt+2, tid);
            CP_COMMIT();
        }

        uint32_t sa = sbase + (uint32_t)(s*STAGE_B);
        #pragma unroll
        for (int ks = 0; ks < 4; ks++){
            uint32_t af[4][4];
            #pragma unroll
            for (int mt = 0; mt < 4; mt++)
                ldsm_x4(af[mt][0], af[mt][1], af[mt][2], af[mt][3],
                        sa + aOff + (uint32_t)(mt*2304 + ks*32));
            uint32_t bf[4][2];
            #pragma unroll
            for (int np = 0; np < 2; np++){
                uint32_t r0, r1, r2, r3;
                ldsm_x4(r0, r1, r2, r3, sa + bOff + (uint32_t)(np*2304 + ks*32));
                bf[np*2][0]   = r0; bf[np*2][1]   = r1;
                bf[np*2+1][0] = r2; bf[np*2+1][1] = r3;
            }
            #pragma unroll
            for (int mt = 0; mt < 4; mt++)
                #pragma unroll
                for (int nt = 0; nt < 4; nt++)
                    mma_f16(c[mt][nt], af[mt], bf[nt]);
        }
    }

    // epilogue. Q gets softmax scale + log2e folded in (exp2-domain softmax).
    float sc = (qkv && z == 0) ? 0.125f*1.44269504088896f : 1.0f;
    #pragma unroll
    for (int mt = 0; mt < 4; mt++){
        #pragma unroll
        for (int nt = 0; nt < 4; nt++){
            int gr = bm0 + wm + mt*16 + (lane >> 2);
            int gc = bn0 + wn + nt*8 + ((lane & 3) << 1);
            if (qkv){
                __half* dst = (z == 0) ? g_q : (z == 1) ? g_k : g_v;
                int bb = gr >> 11, tt = gr & (SEQ - 1);
                int hh = gc >> 6,  dd = gc & (HD - 1);
                size_t off = ((size_t)(bb*NH + hh)*SEQ + tt)*HD + dd;
                *(uint32_t*)(dst + off)         = packh2(c[mt][nt][0]*sc, c[mt][nt][1]*sc);
                *(uint32_t*)(dst + off + 8*HD)  = packh2(c[mt][nt][2]*sc, c[mt][nt][3]*sc);
            } else {
                *(float2*)(Cout + (size_t)gr*DIMC + gc)
                    = make_float2(c[mt][nt][0], c[mt][nt][1]);
                *(float2*)(Cout + (size_t)(gr + 8)*DIMC + gc)
                    = make_float2(c[mt][nt][2], c[mt][nt][3]);
            }
        }
    }
}

// ============================================================================
// causal flash attention: fp16 mma (m16n8k16), exp2-domain fp32 softmax,
// KTILE=64 (softmax bookkeeping amortized over 2x keys), 2-stage cp.async
// double buffer, ldmatrix frags, register-only P re-frag.
// 4 warps x 16 q-rows, QT=64, rows 144 B. Reverse q-tile order (wave balance).
// ============================================================================
#define QT 64
#define KTILE 64
#define ARH 72                 // halves per row (144 B)
#define KVSTRIDE (KTILE*ARH*2) // 18432 B per K (or V) stage

__global__ void __launch_bounds__(128, 3)
attn_f16()
{
    __shared__ __align__(16) __half sQ[QT*ARH];          //  9216 B
    __shared__ __align__(16) __half sK[2][KTILE*ARH];    // 18432 B
    __shared__ __align__(16) __half sV[2][KTILE*ARH];    // 18432 B  -> 46080 B

    int tid  = threadIdx.x;
    int lane = tid & 31;
    int warp = tid >> 5;
    int bh = blockIdx.y;
    int q0 = ((int)gridDim.x - 1 - (int)blockIdx.x) * QT;   // longest first

    const __half* Qg = g_q + (size_t)bh*SEQ*HD;
    const __half* Kg = g_k + (size_t)bh*SEQ*HD;
    const __half* Vg = g_v + (size_t)bh*SEQ*HD;

    uint32_t sQb = smem_u32(sQ);
    uint32_t sK0 = smem_u32(sK[0]);
    uint32_t sV0 = smem_u32(sV[0]);
    int nkt = q0/KTILE + 1;      // >= 1

    // per-lane ldmatrix byte offsets (loop-invariant)
    uint32_t kOff = (uint32_t)(((lane & 7) + ((lane & 16) ? 8 : 0))*144 + ((lane & 8) << 1));
    uint32_t vOff = (uint32_t)(((lane & 7) + ((lane & 8) ? 8 : 0))*144 + ((lane & 16) ? 16 : 0));

    // prologue: Q + KV stage 0 in one group
    #pragma unroll
    for (int p = 0; p < 4; p++){
        int n = tid + p*128;           // 0..511
        int r = n >> 3, ch = n & 7;
        cp16(sQb + (uint32_t)(r*144 + ch*16), Qg + (size_t)(q0 + r)*HD + ch*8);
    }
    #pragma unroll
    for (int p = 0; p < 8; p++){
        int n = tid + p*128;           // 0..1023
        int isV = n >> 9, m = n & 511;
        int r = m >> 3, ch = m & 7;    // r 0..63
        cp16((isV ? sV0 : sK0) + (uint32_t)(r*144 + ch*16),
             (isV ? Vg : Kg) + (size_t)r*HD + ch*8);
    }
    CP_COMMIT();

    uint32_t qf[4][4];
    float o[8][4];
    #pragma unroll
    for (int i = 0; i < 8; i++)
        #pragma unroll
        for (int j = 0; j < 4; j++) o[i][j] = 0.f;
    float m0 = -1e30f, m1 = -1e30f, l0 = 0.f, l1 = 0.f;

    for (int kt = 0; kt < nkt; kt++){
        CP_WAIT(0);            // stage kt (and Q on kt=0) has landed
        __syncthreads();       // all warps done reading the other buffer
        if (kt + 1 < nkt){     // prefetch stage kt+1 into the other buffer
            uint32_t bOf = ((kt+1) & 1) ? (uint32_t)KVSTRIDE : 0u;
            int kb2 = (kt+1)*KTILE;
            #pragma unroll
            for (int p = 0; p < 8; p++){
                int n = tid + p*128;
                int isV = n >> 9, m = n & 511;
                int r = m >> 3, ch = m & 7;
                cp16((isV ? sV0 : sK0) + bOf + (uint32_t)(r*144 + ch*16),
                     (isV ? Vg : Kg) + (size_t)(kb2 + r)*HD + ch*8);
            }
            CP_COMMIT();
        }
        if (kt == 0){
            #pragma unroll
            for (int ks = 0; ks < 4; ks++){
                int row = warp*16 + (lane & 15);
                int col = ks*16 + ((lane & 16) ? 8 : 0);
                ldsm_x4(qf[ks][0], qf[ks][1], qf[ks][2], qf[ks][3],
                        sQb + (uint32_t)(row*144 + col*2));
            }
        }

        int kb = kt*KTILE;
        int wrow0 = q0 + warp*16;
        uint32_t stO = (kt & 1) ? (uint32_t)KVSTRIDE : 0u;
        uint32_t sKb = sK0 + stO;
        uint32_t sVb = sV0 + stO;

        // S = Q @ K^T  (16 q-rows x 64 keys); Q pre-scaled by log2e/8
        float sv[8][4];
        #pragma unroll
        for (int i = 0; i < 8; i++)
            #pragma unroll
            for (int j = 0; j < 4; j++) sv[i][j] = 0.f;
        #pragma unroll
        for (int ks = 0; ks < 4; ks++){
            uint32_t kf[8][2];
            #pragma unroll
            for (int np = 0; np < 4; np++){
                uint32_t r0, r1, r2, r3;
                ldsm_x4(r0, r1, r2, r3, sKb + kOff + (uint32_t)(np*2304 + ks*32));
                kf[np*2][0]   = r0; kf[np*2][1]   = r1;
                kf[np*2+1][0] = r2; kf[np*2+1][1] = r3;
            }
            #pragma unroll
            for (int nt = 0; nt < 8; nt++)
                mma_f16(sv[nt], qf[ks], kf[nt]);
        }

        // causal mask (last tile only: kb == q0)
        int qr0 = wrow0 + (lane >> 2);
        if (kb + KTILE - 1 > wrow0){
            #pragma unroll
            for (int nt = 0; nt < 8; nt++){
                int kc = kb + nt*8 + ((lane & 3) << 1);
                if (kc     > qr0    ) sv[nt][0] = -1e30f;
                if (kc + 1 > qr0    ) sv[nt][1] = -1e30f;
                if (kc     > qr0 + 8) sv[nt][2] = -1e30f;
                if (kc + 1 > qr0 + 8) sv[nt][3] = -1e30f;
            }
        }

        // online softmax, exp2 domain (rows qr0 and qr0+8 per lane-quad)
        float rm0 = -1e30f, rm1 = -1e30f;
        #pragma unroll
        for (int nt = 0; nt < 8; nt++){
            rm0 = fmaxf(rm0, fmaxf(sv[nt][0], sv[nt][1]));
            rm1 = fmaxf(rm1, fmaxf(sv[nt][2], sv[nt][3]));
        }
        rm0 = fmaxf(rm0, __shfl_xor_sync(0xffffffffu, rm0, 1));
        rm0 = fmaxf(rm0, __shfl_xor_sync(0xffffffffu, rm0, 2));
        rm1 = fmaxf(rm1, __shfl_xor_sync(0xffffffffu, rm1, 1));
        rm1 = fmaxf(rm1, __shfl_xor_sync(0xffffffffu, rm1, 2));

        float mn0 = fmaxf(m0, rm0), mn1 = fmaxf(m1, rm1);
        float a0 = ex2(m0 - mn0), a1 = ex2(m1 - mn1);
        float rs0 = 0.f, rs1 = 0.f;
        #pragma unroll
        for (int nt = 0; nt < 8; nt++){
            sv[nt][0] = ex2(sv[nt][0] - mn0);
            sv[nt][1] = ex2(sv[nt][1] - mn0);
            sv[nt][2] = ex2(sv[nt][2] - mn1);
            sv[nt][3] = ex2(sv[nt][3] - mn1);
            rs0 += sv[nt][0] + sv[nt][1];
            rs1 += sv[nt][2] + sv[nt][3];
        }
        rs0 += __shfl_xor_sync(0xffffffffu, rs0, 1);
        rs0 += __shfl_xor_sync(0xffffffffu, rs0, 2);
        rs1 += __shfl_xor_sync(0xffffffffu, rs1, 1);
        rs1 += __shfl_xor_sync(0xffffffffu, rs1, 2);
        l0 = l0*a0 + rs0;
        l1 = l1*a1 + rs1;
        m0 = mn0; m1 = mn1;
        #pragma unroll
        for (int nt = 0; nt < 8; nt++){
            o[nt][0] *= a0; o[nt][1] *= a0;
            o[nt][2] *= a1; o[nt][3] *= a1;
        }

        // P: C-fragment -> A-fragment entirely in registers (4 k16-steps)
        uint32_t pf[4][4];
        #pragma unroll
        for (int j = 0; j < 4; j++){
            pf[j][0] = packh2(sv[2*j][0],   sv[2*j][1]);
            pf[j][1] = packh2(sv[2*j][2],   sv[2*j][3]);
            pf[j][2] = packh2(sv[2*j+1][0], sv[2*j+1][1]);
            pf[j][3] = packh2(sv[2*j+1][2], sv[2*j+1][3]);
        }

        // O += P @ V  (V fragments via ldmatrix.trans)
        #pragma unroll
        for (int j = 0; j < 4; j++){
            uint32_t vf[8][2];
            #pragma unroll
            for (int np = 0; np < 4; np++){
                uint32_t r0, r1, r2, r3;
                ldsm_x4t(r0, r1, r2, r3, sVb + vOff + (uint32_t)(j*2304 + np*32));
                vf[np*2][0]   = r0; vf[np*2][1]   = r1;
                vf[np*2+1][0] = r2; vf[np*2+1][1] = r3;
            }
            #pragma unroll
            for (int nt = 0; nt < 8; nt++)
                mma_f16(o[nt], pf[j], vf[nt]);
        }
    }

    // epilogue: O/l -> g_attn (fp16) [b*T+t][h*64+d]
    float il0 = 1.0f / l0, il1 = 1.0f / l1;
    int b = bh >> 4, h = bh & 15;
    int t0 = q0 + warp*16 + (lane >> 2);
    #pragma unroll
    for (int nt = 0; nt < 8; nt++){
        int d = nt*8 + ((lane & 3) << 1);
        size_t base = ((size_t)(b*SEQ + t0))*DIMC + h*HD + d;
        *(uint32_t*)(g_attn + base)                  = packh2(o[nt][0]*il0, o[nt][1]*il0);
        *(uint32_t*)(g_attn + base + (size_t)8*DIMC) = packh2(o[nt][2]*il1, o[nt][3]*il1);
    }
}

// ---------------- launch ----------------------------------------------------
extern "C" void kernel_launch(void* const* d_in, const int* in_sizes, int n_in,
                              void* d_out, int out_size)
{
    const float* x  = (const float*)d_in[0];
    const float* wq = (const float*)d_in[1];
    const float* wk = (const float*)d_in[2];
    const float* wv = (const float*)d_in[3];
    const float* wo = (const float*)d_in[4];
    float* out = (float*)d_out;

    cudaFuncSetAttribute(gemm_f16, cudaFuncAttributeMaxDynamicSharedMemorySize, GSMEM_BYTES);

    // fp32 -> fp16 converts
    int n8x = MTOT*DIMC/8;     // 1048576
    int n8w = DIMC*DIMC/8;     // 131072
    cvt_x_f16<<<(n8x+255)/256, 256>>>(x, n8x);
    cvt_w_f16<<<dim3((n8w+255)/256, 4), 256>>>(wq, wk, wv, wo, n8w);

    dim3 gq(DIMC/BN, MTOT/BM, 3);   // fused QKV
    gemm_f16<<<gq, 256, GSMEM_BYTES>>>(nullptr, 1);
    attn_f16<<<dim3(SEQ/QT, BATCH*NH), 128>>>();
    dim3 go(DIMC/BN, MTOT/BM, 1);
    gemm_f16<<<go, 256, GSMEM_BYTES>>>(out, 0);
}

// round 17
// speedup vs baseline: 1.0217x; 1.0217x over previous
#include <cuda_runtime.h>
#include <cuda_fp16.h>
#include <cstdint>

#define DIMC  1024
#define NH    16
#define HD    64
#define BATCH 4
#define SEQ   2048
#define MTOT  (BATCH*SEQ)   // 8192

// ---------------- scratch (device globals; no allocation allowed) ----------
__device__ __half g_xh[(size_t)MTOT*DIMC];        // x in fp16
__device__ __half g_wh[(size_t)4*DIMC*DIMC];      // wq,wk,wv,wo in fp16
__device__ __half g_q[(size_t)MTOT*DIMC];         // [b*NH+h][t][d], pre-scaled by log2e/8
__device__ __half g_k[(size_t)MTOT*DIMC];
__device__ __half g_v[(size_t)MTOT*DIMC];
__device__ __half g_attn[(size_t)MTOT*DIMC];      // [b*T+t][h*64+d]

// ---------------- helpers ---------------------------------------------------
__device__ __forceinline__ uint32_t smem_u32(const void* p){
    uint32_t a;
    asm("{ .reg .u64 t; cvta.to.shared.u64 t, %1; cvt.u32.u64 %0, t; }" : "=r"(a) : "l"(p));
    return a;
}
// pack two f32 -> f16x2 (lo, hi). PTX cvt f16x2: first source -> HIGH half.
__device__ __forceinline__ uint32_t packh2(float lo, float hi){
    uint32_t d;
    asm("cvt.rn.f16x2.f32 %0, %1, %2;" : "=r"(d) : "f"(hi), "f"(lo));
    return d;
}
__device__ __forceinline__ float ex2(float x){
    float r; asm("ex2.approx.f32 %0, %1;" : "=f"(r) : "f"(x)); return r;
}
__device__ __forceinline__ void cp16(uint32_t dst, const void* src){
    asm volatile("cp.async.cg.shared.global [%0], [%1], 16;" :: "r"(dst), "l"(src));
}
#define CP_COMMIT() asm volatile("cp.async.commit_group;" ::: "memory")
#define CP_WAIT(n)  asm volatile("cp.async.wait_group %0;" :: "n"(n) : "memory")

__device__ __forceinline__ void ldsm_x4(uint32_t& r0, uint32_t& r1, uint32_t& r2, uint32_t& r3,
                                        uint32_t addr){
    asm volatile("ldmatrix.sync.aligned.m8n8.x4.shared.b16 {%0,%1,%2,%3}, [%4];"
                 : "=r"(r0), "=r"(r1), "=r"(r2), "=r"(r3) : "r"(addr));
}
__device__ __forceinline__ void ldsm_x4t(uint32_t& r0, uint32_t& r1, uint32_t& r2, uint32_t& r3,
                                         uint32_t addr){
    asm volatile("ldmatrix.sync.aligned.m8n8.x4.trans.shared.b16 {%0,%1,%2,%3}, [%4];"
                 : "=r"(r0), "=r"(r1), "=r"(r2), "=r"(r3) : "r"(addr));
}
__device__ __forceinline__ void mma_f16(float c[4], const uint32_t a[4], const uint32_t b[2]){
    asm volatile(
        "mma.sync.aligned.m16n8k16.row.col.f32.f16.f16.f32 "
        "{%0,%1,%2,%3}, {%4,%5,%6,%7}, {%8,%9}, {%0,%1,%2,%3};"
        : "+f"(c[0]), "+f"(c[1]), "+f"(c[2]), "+f"(c[3])
        : "r"(a[0]), "r"(a[1]), "r"(a[2]), "r"(a[3]), "r"(b[0]), "r"(b[1]));
}

// ---------------- fp32 -> fp16 converts --------------------------------------
__global__ void cvt_x_f16(const float* __restrict__ src, int n8){
    int i = blockIdx.x*blockDim.x + threadIdx.x;
    if (i >= n8) return;
    float4 a = ((const float4*)src)[2*i];
    float4 b = ((const float4*)src)[2*i + 1];
    uint4 o;
    o.x = packh2(a.x, a.y); o.y = packh2(a.z, a.w);
    o.z = packh2(b.x, b.y); o.w = packh2(b.z, b.w);
    ((uint4*)g_xh)[i] = o;
}
__global__ void cvt_w_f16(const float* __restrict__ w0, const float* __restrict__ w1,
                          const float* __restrict__ w2, const float* __restrict__ w3,
                          int n8){
    int i = blockIdx.x*blockDim.x + threadIdx.x;
    if (i >= n8) return;
    int z = blockIdx.y;
    const float* src = (z == 0) ? w0 : (z == 1) ? w1 : (z == 2) ? w2 : w3;
    __half* dst = g_wh + (size_t)z*DIMC*DIMC;
    float4 a = ((const float4*)src)[2*i];
    float4 b = ((const float4*)src)[2*i + 1];
    uint4 o;
    o.x = packh2(a.x, a.y); o.y = packh2(a.z, a.w);
    o.z = packh2(b.x, b.y); o.w = packh2(b.z, b.w);
    ((uint4*)dst)[i] = o;
}

// ============================================================================
// fp16 GEMM:  C[M,N] = A[M,K] @ W[N,K]^T   (both K-major fp16, K=1024)
// 128x128 tile, 8 warps (2x4), warp tile 64x32, BK=64 (16 k-iterations),
// 2-stage cp.async double buffer (best-measured config), rows 144 B
// (attn-proven conflict-free ldmatrix layout). 16 warps/SM (2 CTAs x 8 warps).
// One __syncthreads per k-iteration (the leading wait+sync closes the WAR).
// ============================================================================
#define BM 128
#define BN 128
#define GK 64
#define GNT2 (DIMC/GK)        // 16
#define GRB 144               // bytes per smem row (64 halves + 8 pad)
#define ATB (BM*GRB)          // bytes per operand tile: 18432
#define STAGE_B (2*ATB)       // 36864 B per stage
#define GSMEM_BYTES (2*STAGE_B)   // 73728

__device__ __forceinline__ void g_fill(uint32_t sbase, int st,
                                       const __half* __restrict__ A,
                                       const __half* __restrict__ W,
                                       int bm0, int bn0, int kt, int tid){
    uint32_t sd = sbase + (uint32_t)(st*STAGE_B);
    #pragma unroll
    for (int p = 0; p < 8; p++){
        int n = tid + p*256;            // 0..2047
        int op = n >> 10, m = n & 1023; // op 0=A, 1=B
        int r = m >> 3, ch = m & 7;     // row 0..127, 16B chunk 0..7
        const __half* src = op ? (W + (size_t)(bn0 + r)*DIMC + kt*GK + ch*8)
                               : (A + (size_t)(bm0 + r)*DIMC + kt*GK + ch*8);
        cp16(sd + (uint32_t)(op*ATB + r*GRB + ch*16), src);
    }
}

__global__ void __launch_bounds__(256, 2)
gemm_f16(float* __restrict__ Cout, int qkv)
{
    extern __shared__ __align__(16) __half sm[];
    uint32_t sbase = smem_u32(sm);
    int tid = threadIdx.x, lane = tid & 31, warp = tid >> 5;
    int bm0 = blockIdx.y*BM, bn0 = blockIdx.x*BN;
    int z = qkv ? (int)blockIdx.z : 3;
    const __half* A = qkv ? g_xh : g_attn;
    const __half* W = g_wh + (size_t)z*DIMC*DIMC;
    int wm = (warp >> 2)*64, wn = (warp & 3)*32;   // 2x4 warp grid, tile 64x32

    // per-lane ldmatrix byte offsets (attn-proven patterns, loop-invariant)
    uint32_t aOff = (uint32_t)((wm + (lane & 15))*GRB + ((lane & 16) ? 16 : 0));
    uint32_t bOff = (uint32_t)(ATB + (wn + (lane & 7) + ((lane & 16) ? 8 : 0))*GRB
                               + ((lane & 8) << 1));

    float c[4][4][4];
    #pragma unroll
    for (int i = 0; i < 4; i++)
        #pragma unroll
        for (int j = 0; j < 4; j++)
            #pragma unroll
            for (int k = 0; k < 4; k++) c[i][j][k] = 0.f;

    g_fill(sbase, 0, A, W, bm0, bn0, 0, tid); CP_COMMIT();

    for (int kt = 0; kt < GNT2; kt++){
        CP_WAIT(0);
        __syncthreads();    // stage kt landed AND all warps done reading stage kt-1
        if (kt + 1 < GNT2){
            g_fill(sbase, (kt+1) & 1, A, W, bm0, bn0, kt+1, tid);
            CP_COMMIT();
        }

        uint32_t sa = sbase + (uint32_t)((kt & 1)*STAGE_B);
        #pragma unroll
        for (int ks = 0; ks < 4; ks++){
            uint32_t af[4][4];
            #pragma unroll
            for (int mt = 0; mt < 4; mt++)
                ldsm_x4(af[mt][0], af[mt][1], af[mt][2], af[mt][3],
                        sa + aOff + (uint32_t)(mt*2304 + ks*32));
            uint32_t bf[4][2];
            #pragma unroll
            for (int np = 0; np < 2; np++){
                uint32_t r0, r1, r2, r3;
                ldsm_x4(r0, r1, r2, r3, sa + bOff + (uint32_t)(np*2304 + ks*32));
                bf[np*2][0]   = r0; bf[np*2][1]   = r1;
                bf[np*2+1][0] = r2; bf[np*2+1][1] = r3;
            }
            #pragma unroll
            for (int mt = 0; mt < 4; mt++)
                #pragma unroll
                for (int nt = 0; nt < 4; nt++)
                    mma_f16(c[mt][nt], af[mt], bf[nt]);
        }
    }

    // epilogue. Q gets softmax scale + log2e folded in (exp2-domain softmax).
    float sc = (qkv && z == 0) ? 0.125f*1.44269504088896f : 1.0f;
    #pragma unroll
    for (int mt = 0; mt < 4; mt++){
        #pragma unroll
        for (int nt = 0; nt < 4; nt++){
            int gr = bm0 + wm + mt*16 + (lane >> 2);
            int gc = bn0 + wn + nt*8 + ((lane & 3) << 1);
            if (qkv){
                __half* dst = (z == 0) ? g_q : (z == 1) ? g_k : g_v;
                int bb = gr >> 11, tt = gr & (SEQ - 1);
                int hh = gc >> 6,  dd = gc & (HD - 1);
                size_t off = ((size_t)(bb*NH + hh)*SEQ + tt)*HD + dd;
                *(uint32_t*)(dst + off)         = packh2(c[mt][nt][0]*sc, c[mt][nt][1]*sc);
                *(uint32_t*)(dst + off + 8*HD)  = packh2(c[mt][nt][2]*sc, c[mt][nt][3]*sc);
            } else {
                *(float2*)(Cout + (size_t)gr*DIMC + gc)
                    = make_float2(c[mt][nt][0], c[mt][nt][1]);
                *(float2*)(Cout + (size_t)(gr + 8)*DIMC + gc)
                    = make_float2(c[mt][nt][2], c[mt][nt][3]);
            }
        }
    }
}

// ============================================================================
// causal flash attention: fp16 mma (m16n8k16), exp2-domain fp32 softmax,
// KTILE=64 (softmax bookkeeping amortized over 2x keys), 2-stage cp.async
// double buffer, ldmatrix frags, register-only P re-frag.
// 4 warps x 16 q-rows, QT=64, rows 144 B. Reverse q-tile order (wave balance).
// ============================================================================
#define QT 64
#define KTILE 64
#define ARH 72                 // halves per row (144 B)
#define KVSTRIDE (KTILE*ARH*2) // 18432 B per K (or V) stage

__global__ void __launch_bounds__(128, 3)
attn_f16()
{
    __shared__ __align__(16) __half sQ[QT*ARH];          //  9216 B
    __shared__ __align__(16) __half sK[2][KTILE*ARH];    // 18432 B
    __shared__ __align__(16) __half sV[2][KTILE*ARH];    // 18432 B  -> 46080 B

    int tid  = threadIdx.x;
    int lane = tid & 31;
    int warp = tid >> 5;
    int bh = blockIdx.y;
    int q0 = ((int)gridDim.x - 1 - (int)blockIdx.x) * QT;   // longest first

    const __half* Qg = g_q + (size_t)bh*SEQ*HD;
    const __half* Kg = g_k + (size_t)bh*SEQ*HD;
    const __half* Vg = g_v + (size_t)bh*SEQ*HD;

    uint32_t sQb = smem_u32(sQ);
    uint32_t sK0 = smem_u32(sK[0]);
    uint32_t sV0 = smem_u32(sV[0]);
    int nkt = q0/KTILE + 1;      // >= 1

    // per-lane ldmatrix byte offsets (loop-invariant)
    uint32_t kOff = (uint32_t)(((lane & 7) + ((lane & 16) ? 8 : 0))*144 + ((lane & 8) << 1));
    uint32_t vOff = (uint32_t)(((lane & 7) + ((lane & 8) ? 8 : 0))*144 + ((lane & 16) ? 16 : 0));

    // prologue: Q + KV stage 0 in one group
    #pragma unroll
    for (int p = 0; p < 4; p++){
        int n = tid + p*128;           // 0..511
        int r = n >> 3, ch = n & 7;
        cp16(sQb + (uint32_t)(r*144 + ch*16), Qg + (size_t)(q0 + r)*HD + ch*8);
    }
    #pragma unroll
    for (int p = 0; p < 8; p++){
        int n = tid + p*128;           // 0..1023
        int isV = n >> 9, m = n & 511;
        int r = m >> 3, ch = m & 7;    // r 0..63
        cp16((isV ? sV0 : sK0) + (uint32_t)(r*144 + ch*16),
             (isV ? Vg : Kg) + (size_t)r*HD + ch*8);
    }
    CP_COMMIT();

    uint32_t qf[4][4];
    float o[8][4];
    #pragma unroll
    for (int i = 0; i < 8; i++)
        #pragma unroll
        for (int j = 0; j < 4; j++) o[i][j] = 0.f;
    float m0 = -1e30f, m1 = -1e30f, l0 = 0.f, l1 = 0.f;

    for (int kt = 0; kt < nkt; kt++){
        CP_WAIT(0);            // stage kt (and Q on kt=0) has landed
        __syncthreads();       // all warps done reading the other buffer
        if (kt + 1 < nkt){     // prefetch stage kt+1 into the other buffer
            uint32_t bOf = ((kt+1) & 1) ? (uint32_t)KVSTRIDE : 0u;
            int kb2 = (kt+1)*KTILE;
            #pragma unroll
            for (int p = 0; p < 8; p++){
                int n = tid + p*128;
                int isV = n >> 9, m = n & 511;
                int r = m >> 3, ch = m & 7;
                cp16((isV ? sV0 : sK0) + bOf + (uint32_t)(r*144 + ch*16),
                     (isV ? Vg : Kg) + (size_t)(kb2 + r)*HD + ch*8);
            }
            CP_COMMIT();
        }
        if (kt == 0){
            #pragma unroll
            for (int ks = 0; ks < 4; ks++){
                int row = warp*16 + (lane & 15);
                int col = ks*16 + ((lane & 16) ? 8 : 0);
                ldsm_x4(qf[ks][0], qf[ks][1], qf[ks][2], qf[ks][3],
                        sQb + (uint32_t)(row*144 + col*2));
            }
        }

        int kb = kt*KTILE;
        int wrow0 = q0 + warp*16;
        uint32_t stO = (kt & 1) ? (uint32_t)KVSTRIDE : 0u;
        uint32_t sKb = sK0 + stO;
        uint32_t sVb = sV0 + stO;

        // S = Q @ K^T  (16 q-rows x 64 keys); Q pre-scaled by log2e/8
        float sv[8][4];
        #pragma unroll
        for (int i = 0; i < 8; i++)
            #pragma unroll
            for (int j = 0; j < 4; j++) sv[i][j] = 0.f;
        #pragma unroll
        for (int ks = 0; ks < 4; ks++){
            uint32_t kf[8][2];
            #pragma unroll
            for (int np = 0; np < 4; np++){
                uint32_t r0, r1, r2, r3;
                ldsm_x4(r0, r1, r2, r3, sKb + kOff + (uint32_t)(np*2304 + ks*32));
                kf[np*2][0]   = r0; kf[np*2][1]   = r1;
                kf[np*2+1][0] = r2; kf[np*2+1][1] = r3;
            }
            #pragma unroll
            for (int nt = 0; nt < 8; nt++)
                mma_f16(sv[nt], qf[ks], kf[nt]);
        }

        // causal mask (last tile only: kb == q0)
        int qr0 = wrow0 + (lane >> 2);
        if (kb + KTILE - 1 > wrow0){
            #pragma unroll
            for (int nt = 0; nt < 8; nt++){
                int kc = kb + nt*8 + ((lane & 3) << 1);
                if (kc     > qr0    ) sv[nt][0] = -1e30f;
                if (kc + 1 > qr0    ) sv[nt][1] = -1e30f;
                if (kc     > qr0 + 8) sv[nt][2] = -1e30f;
                if (kc + 1 > qr0 + 8) sv[nt][3] = -1e30f;
            }
        }

        // online softmax, exp2 domain (rows qr0 and qr0+8 per lane-quad)
        float rm0 = -1e30f, rm1 = -1e30f;
        #pragma unroll
        for (int nt = 0; nt < 8; nt++){
            rm0 = fmaxf(rm0, fmaxf(sv[nt][0], sv[nt][1]));
            rm1 = fmaxf(rm1, fmaxf(sv[nt][2], sv[nt][3]));
        }
        rm0 = fmaxf(rm0, __shfl_xor_sync(0xffffffffu, rm0, 1));
        rm0 = fmaxf(rm0, __shfl_xor_sync(0xffffffffu, rm0, 2));
        rm1 = fmaxf(rm1, __shfl_xor_sync(0xffffffffu, rm1, 1));
        rm1 = fmaxf(rm1, __shfl_xor_sync(0xffffffffu, rm1, 2));

        float mn0 = fmaxf(m0, rm0), mn1 = fmaxf(m1, rm1);
        float a0 = ex2(m0 - mn0), a1 = ex2(m1 - mn1);
        float rs0 = 0.f, rs1 = 0.f;
        #pragma unroll
        for (int nt = 0; nt < 8; nt++){
            sv[nt][0] = ex2(sv[nt][0] - mn0);
            sv[nt][1] = ex2(sv[nt][1] - mn0);
            sv[nt][2] = ex2(sv[nt][2] - mn1);
            sv[nt][3] = ex2(sv[nt][3] - mn1);
            rs0 += sv[nt][0] + sv[nt][1];
            rs1 += sv[nt][2] + sv[nt][3];
        }
        rs0 += __shfl_xor_sync(0xffffffffu, rs0, 1);
        rs0 += __shfl_xor_sync(0xffffffffu, rs0, 2);
        rs1 += __shfl_xor_sync(0xffffffffu, rs1, 1);
        rs1 += __shfl_xor_sync(0xffffffffu, rs1, 2);
        l0 = l0*a0 + rs0;
        l1 = l1*a1 + rs1;
        m0 = mn0; m1 = mn1;
        #pragma unroll
        for (int nt = 0; nt < 8; nt++){
            o[nt][0] *= a0; o[nt][1] *= a0;
            o[nt][2] *= a1; o[nt][3] *= a1;
        }

        // P: C-fragment -> A-fragment entirely in registers (4 k16-steps)
        uint32_t pf[4][4];
        #pragma unroll
        for (int j = 0; j < 4; j++){
            pf[j][0] = packh2(sv[2*j][0],   sv[2*j][1]);
            pf[j][1] = packh2(sv[2*j][2],   sv[2*j][3]);
            pf[j][2] = packh2(sv[2*j+1][0], sv[2*j+1][1]);
            pf[j][3] = packh2(sv[2*j+1][2], sv[2*j+1][3]);
        }

        // O += P @ V  (V fragments via ldmatrix.trans)
        #pragma unroll
        for (int j = 0; j < 4; j++){
            uint32_t vf[8][2];
            #pragma unroll
            for (int np = 0; np < 4; np++){
                uint32_t r0, r1, r2, r3;
                ldsm_x4t(r0, r1, r2, r3, sVb + vOff + (uint32_t)(j*2304 + np*32));
                vf[np*2][0]   = r0; vf[np*2][1]   = r1;
                vf[np*2+1][0] = r2; vf[np*2+1][1] = r3;
            }
            #pragma unroll
            for (int nt = 0; nt < 8; nt++)
                mma_f16(o[nt], pf[j], vf[nt]);
        }
    }

    // epilogue: O/l -> g_attn (fp16) [b*T+t][h*64+d]
    float il0 = 1.0f / l0, il1 = 1.0f / l1;
    int b = bh >> 4, h = bh & 15;
    int t0 = q0 + warp*16 + (lane >> 2);
    #pragma unroll
    for (int nt = 0; nt < 8; nt++){
        int d = nt*8 + ((lane & 3) << 1);
        size_t base = ((size_t)(b*SEQ + t0))*DIMC + h*HD + d;
        *(uint32_t*)(g_attn + base)                  = packh2(o[nt][0]*il0, o[nt][1]*il0);
        *(uint32_t*)(g_attn + base + (size_t)8*DIMC) = packh2(o[nt][2]*il1, o[nt][3]*il1);
    }
}

// ---------------- launch ----------------------------------------------------
extern "C" void kernel_launch(void* const* d_in, const int* in_sizes, int n_in,
                              void* d_out, int out_size)
{
    const float* x  = (const float*)d_in[0];
    const float* wq = (const float*)d_in[1];
    const float* wk = (const float*)d_in[2];
    const float* wv = (const float*)d_in[3];
    const float* wo = (const float*)d_in[4];
    float* out = (float*)d_out;

    cudaFuncSetAttribute(gemm_f16, cudaFuncAttributeMaxDynamicSharedMemorySize, GSMEM_BYTES);

    // fp32 -> fp16 converts
    int n8x = MTOT*DIMC/8;     // 1048576
    int n8w = DIMC*DIMC/8;     // 131072
    cvt_x_f16<<<(n8x+255)/256, 256>>>(x, n8x);
    cvt_w_f16<<<dim3((n8w+255)/256, 4), 256>>>(wq, wk, wv, wo, n8w);

    dim3 gq(DIMC/BN, MTOT/BM, 3);   // fused QKV
    gemm_f16<<<gq, 256, GSMEM_BYTES>>>(nullptr, 1);
    attn_f16<<<dim3(SEQ/QT, BATCH*NH), 128>>>();
    dim3 go(DIMC/BN, MTOT/BM, 1);
    gemm_f16<<<go, 256, GSMEM_BYTES>>>(out, 0);
}